// round 13
// baseline (speedup 1.0000x reference)
#include <cuda_runtime.h>
#include <cuda_fp16.h>
#include <math.h>

#define BB 2
#define KK 256
#define RR 32
#define DD 192
#define NH 6
#define DH 32
#define NTOK 1024   // 32*32 L4 tokens per batch

// ---------------- scratch (device globals; no allocs allowed) ----------------
__device__ __half  d_ft0[(size_t)BB*NH*128*128*32];  // level0 channels-last fp16
__device__ __half  d_ft1[(size_t)BB*NH*64*64*32];    // level1
__device__ __half  d_ft2[(size_t)BB*NH*32*32*32];    // level2
__device__ float   d_gpre[(size_t)BB*NTOK*DD];       // g @ W_u[:,192:384]
__device__ float   d_hpre[(size_t)BB*KK*DD];         // h @ W_u[:,0:192] + b_u
__device__ float   d_wuT [(size_t)416*192];          // W_u^T  [c][d]
__device__ float4  d_wdQ [(size_t)96*216];           // (c2,o): (w2c,w2c,w2c+1,w2c+1)
__device__ float4  d_woQ [(size_t)96*192];           // same for W_o

// ---------------- f32x2 packed-FMA helpers (Blackwell) ------------------------
__device__ __forceinline__ void fma2(unsigned long long& d, unsigned long long a,
                                     unsigned long long b) {
    asm("fma.rn.f32x2 %0, %1, %2, %0;" : "+l"(d) : "l"(a), "l"(b));
}
__device__ __forceinline__ float2 unpack2(unsigned long long v) {
    float2 r;
    asm("mov.b64 {%0, %1}, %2;" : "=f"(r.x), "=f"(r.y) : "l"(v));
    return r;
}
// fast tanh via MUFU EX2 (abs err ~1e-6; exact saturation at +-inf)
__device__ __forceinline__ float ftanh(float x) {
    float e = __expf(2.f * x);
    return 1.f - __fdividef(2.f, e + 1.f);
}
// 16B async copy gmem -> smem
__device__ __forceinline__ void cp_async16(unsigned int dst, const void* src) {
    asm volatile("cp.async.ca.shared.global [%0], [%1], 16;" :: "r"(dst), "l"(src));
}
__device__ __forceinline__ void cp_commit() {
    asm volatile("cp.async.commit_group;");
}
__device__ __forceinline__ void cp_wait_all() {
    asm volatile("cp.async.wait_group 0;");
}

// ---------------- weight prep: transposed / dup-quad layouts -----------------
__global__ void wprep_kernel(const float* __restrict__ wu,
                             const float* __restrict__ wd,
                             const float* __restrict__ wa,
                             const float* __restrict__ wo)
{
    int i0 = blockIdx.x * blockDim.x + threadIdx.x;
    int stride = gridDim.x * blockDim.x;
    for (int i = i0; i < 416*192; i += stride) {
        int c = i / 192, d = i - c*192;
        d_wuT[i] = wu[(size_t)d*416 + c];
    }
    for (int i = i0; i < 96*216; i += stride) {
        int c2 = i / 216, o = i - c2*216;
        int c = 2*c2;
        float v0 = (o < 144) ? wd[(size_t)o*192 + c]     : wa[(size_t)(o-144)*192 + c];
        float v1 = (o < 144) ? wd[(size_t)o*192 + c + 1] : wa[(size_t)(o-144)*192 + c + 1];
        d_wdQ[i] = make_float4(v0, v0, v1, v1);
    }
    for (int i = i0; i < 96*192; i += stride) {
        int c2 = i / 192, o = i - c2*192;
        int c = 2*c2;
        float v0 = wo[(size_t)o*192 + c];
        float v1 = wo[(size_t)o*192 + c + 1];
        d_woQ[i] = make_float4(v0, v0, v1, v1);
    }
}

// ---------------- merged precompute: X @ WuT slice ---------------------------
__global__ void __launch_bounds__(192)
pre_merged_kernel(const float* __restrict__ g, const float* __restrict__ h,
                  const float* __restrict__ bias)
{
    __shared__ float xs[32*192];      // row-major [r][c]
    int bx = blockIdx.x;
    const float* X; float* outp; int colOff, r0;
    bool useBias;
    if (bx < 64) { X = g; outp = d_gpre; colOff = 192; r0 = bx*32; useBias = false; }
    else         { X = h; outp = d_hpre; colOff = 0;   r0 = (bx-64)*32; useBias = true; }
    int tid = threadIdx.x;
    for (int i = tid; i < 32*192; i += 192)
        xs[i] = X[(size_t)r0*192 + i];
    __syncthreads();
    int rg = tid & 3;                 // adjacent lanes share cg -> LDG dedup
    int cg = tid >> 2;                // 0..47
    int rr0 = rg * 8;
    float acc[4][8];
    #pragma unroll
    for (int j = 0; j < 4; ++j)
        #pragma unroll
        for (int q = 0; q < 8; ++q) acc[j][q] = 0.f;
    const float* wbase = d_wuT + (size_t)colOff*192 + cg;
    for (int c = 0; c < 192; ++c) {
        float wv[4];
        #pragma unroll
        for (int j = 0; j < 4; ++j) wv[j] = wbase[c*192 + 48*j];
        #pragma unroll
        for (int q = 0; q < 8; ++q) {
            float xv = xs[(rr0 + q)*192 + c];
            #pragma unroll
            for (int j = 0; j < 4; ++j) acc[j][q] += xv * wv[j];
        }
    }
    #pragma unroll
    for (int j = 0; j < 4; ++j) {
        int col = cg + 48*j;
        float bb = useBias ? bias[col] : 0.f;
        #pragma unroll
        for (int q = 0; q < 8; ++q)
            outp[(size_t)(r0 + rr0 + q)*192 + col] = acc[j][q] + bb;
    }
}

// ---------------- merged feature transpose -----------------------------------
__global__ void transpose_merged_kernel(const float* __restrict__ L2p,
                                        const float* __restrict__ L3p,
                                        const float* __restrict__ L4p)
{
    __shared__ float s[32][33];
    int bid = blockIdx.x;
    const float* in; __half* outp; int Hl, Wl, xb, y, bh;
    if (bid < 6144) {
        Hl = Wl = 128; in = L2p; outp = d_ft0;
        int t = bid; xb = t & 3; t >>= 2; y = t & 127; bh = t >> 7;
    } else if (bid < 7680) {
        Hl = Wl = 64; in = L3p; outp = d_ft1;
        int t = bid - 6144; xb = t & 1; t >>= 1; y = t & 63; bh = t >> 6;
    } else {
        Hl = Wl = 32; in = L4p; outp = d_ft2;
        int t = bid - 7680; xb = 0; y = t & 31; bh = t >> 5;
    }
    int x0 = xb * 32;
    int b = bh / NH, hh = bh % NH;
    const float* base = in + (((size_t)b*DD + hh*DH) * Hl + y) * Wl;
    #pragma unroll
    for (int ci = threadIdx.y; ci < 32; ci += 8)
        s[ci][threadIdx.x] = base[(size_t)ci * Hl * Wl + x0 + threadIdx.x];
    __syncthreads();
    __half* ob = outp + (((size_t)bh * Hl + y) * Wl) * 32;
    #pragma unroll
    for (int xi = threadIdx.y; xi < 32; xi += 8)
        ob[(size_t)(x0 + xi) * 32 + threadIdx.x] = __float2half(s[threadIdx.x][xi]);
}

// ---------------- main fused kernel (cp.async staged dup-quad weights) -------
#define SM_UT   0          // u_t [c*34 + r], 192*34 = 6528  (reused as ht)
#define SM_OFFS 6528       // offs [32*144] = 4608 (phi aliases; staging slots here)
#define SM_PHI  6528
#define SM_WTS  11136      // wts [32*72] = 2304 (LN partials alias; staging tail)
#define SM_AX   13440
#define SM_AY   13472
#define SM_IDX  13504
#define SM_MU   13536
#define SM_RS   13568
#define SM_TOTF 13600

__global__ void __launch_bounds__(256, 4)
main_kernel(const int*   __restrict__ top_indices,
            const float* __restrict__ qc,
            const float* __restrict__ ln_g,
            const float* __restrict__ ln_b,
            const float* __restrict__ w_delta_b,
            const float* __restrict__ w_a_b,
            const float* __restrict__ w_o_b,
            const float* __restrict__ e_def,
            float* __restrict__ out)
{
    extern __shared__ float sm[];
    float* u_t  = sm + SM_UT;     // [c*34 + r]
    float* offs = sm + SM_OFFS;
    float* phi  = sm + SM_PHI;
    float* wts  = sm + SM_WTS;
    float* ax_s = sm + SM_AX;
    float* ay_s = sm + SM_AY;
    int*   idx_s = (int*)(sm + SM_IDX);
    float* mu_s = sm + SM_MU;
    float* rs_s = sm + SM_RS;

    int tid  = threadIdx.x;
    int lane = tid & 31;
    int wid  = tid >> 5;
    int bk   = blockIdx.x;         // b*256 + k
    int b    = bk >> 8;

    // ---- anchors ----
    if (tid < 32) {
        int id = top_indices[(size_t)bk * RR + tid];
        idx_s[tid] = id;
        ax_s[tid] = (float)(id & 31) * 32.f + 16.f;
        ay_s[tid] = (float)(id >> 5) * 32.f + 16.f;
    }
    __syncthreads();

    // ---- fourier PE (fast sincos) ----
    {
        int r = tid >> 3, j = tid & 7;
        float qx = qc[(size_t)bk*2 + 0];
        float qy = qc[(size_t)bk*2 + 1];
        float dxn  = (ax_s[r] - qx) * (1.f/1024.f);
        float dyn_ = (ay_s[r] - qy) * (1.f/1024.f);
        float f = (float)(1 << j);
        float xa = (dxn  * f) * 6.283185307179586f;
        float ya = (dyn_ * f) * 6.283185307179586f;
        float sx, cx, sy, cy;
        __sincosf(xa, &sx, &cx);
        __sincosf(ya, &sy, &cy);
        phi[r*32 + j]      = sx;
        phi[r*32 + 8 + j]  = cx;
        phi[r*32 + 16 + j] = sy;
        phi[r*32 + 24 + j] = cy;
    }
    __syncthreads();

    // ---- phase A: gelu(hpre + gpre[idx] + phi @ Wphi^T), two 16-wide K-chunks
    if (tid < 192) {
        {
            float w16[16];
            #pragma unroll
            for (int i = 0; i < 16; ++i)
                w16[i] = d_wuT[(size_t)(384 + i)*192 + tid];
            #pragma unroll 2
            for (int r = 0; r < 32; ++r) {
                const float4* ph = (const float4*)(phi + r*32);
                float acc = 0.f;
                #pragma unroll
                for (int c4 = 0; c4 < 4; ++c4) {
                    float4 pv = ph[c4];
                    acc += pv.x*w16[4*c4] + pv.y*w16[4*c4+1]
                         + pv.z*w16[4*c4+2] + pv.w*w16[4*c4+3];
                }
                u_t[tid*34 + r] = acc;
            }
        }
        {
            float w16[16];
            #pragma unroll
            for (int i = 0; i < 16; ++i)
                w16[i] = d_wuT[(size_t)(400 + i)*192 + tid];
            float hbase = d_hpre[(size_t)bk*192 + tid];
            for (int rb = 0; rb < 32; rb += 4) {
                float gv[4];
                #pragma unroll
                for (int q = 0; q < 4; ++q)
                    gv[q] = d_gpre[((size_t)(b*NTOK + idx_s[rb + q])) * 192 + tid];
                #pragma unroll
                for (int q = 0; q < 4; ++q) {
                    int r = rb + q;
                    float acc = u_t[tid*34 + r] + hbase + gv[q];
                    const float4* ph = (const float4*)(phi + r*32 + 16);
                    #pragma unroll
                    for (int c4 = 0; c4 < 4; ++c4) {
                        float4 pv = ph[c4];
                        acc += pv.x*w16[4*c4] + pv.y*w16[4*c4+1]
                             + pv.z*w16[4*c4+2] + pv.w*w16[4*c4+3];
                    }
                    float gel = 0.5f * acc * (1.f + erff(acc * 0.70710678118654752f));
                    u_t[tid*34 + r] = gel;
                }
            }
        }
    }
    __syncthreads();

    // ---- LN stats ----
    {
        float s1 = 0.f, s2 = 0.f;
        int c0 = wid * 24;
        for (int cc = c0; cc < c0 + 24; ++cc) {
            float v = u_t[cc*34 + lane];
            s1 += v; s2 += v*v;
        }
        wts[wid*32 + lane]       = s1;
        wts[256 + wid*32 + lane] = s2;
    }
    __syncthreads();
    if (tid < 32) {
        float s1 = 0.f, s2 = 0.f;
        #pragma unroll
        for (int w = 0; w < 8; ++w) {
            s1 += wts[w*32 + tid];
            s2 += wts[256 + w*32 + tid];
        }
        float mu  = s1 * (1.f/192.f);
        float var = s2 * (1.f/192.f) - mu*mu;
        mu_s[tid] = mu;
        rs_s[tid] = rsqrtf(var + 1e-5f);
    }
    __syncthreads();

    // ---- LN apply ----
    if (tid < 192) {
        float gg = ln_g[tid], bb = ln_b[tid];
        #pragma unroll 4
        for (int r = 0; r < 32; ++r) {
            float v = u_t[tid*34 + r];
            u_t[tid*34 + r] = (v - mu_s[r]) * rs_s[r] * gg + bb;
        }
    }
    __syncthreads();

    // ---- phase B: [32x192] @ [192x216]; staged dup-quad weights -------------
    // stage = 4 c2 x 216 float4 = 13824B; 2 slots in dead offs+wts (27648B)
    {
        const char* wsrc = (const char*)d_wdQ;
        unsigned int offs_sh = (unsigned int)__cvta_generic_to_shared(offs);
        for (int ch = tid; ch < 864; ch += 256)
            cp_async16(offs_sh + ch*16, wsrc + ch*16);
        cp_commit();

        int rg = tid & 3;
        int cg = tid >> 2;            // 0..53
        int r0 = rg * 8;
        unsigned long long acc[4][4];
        #pragma unroll
        for (int j = 0; j < 4; ++j)
            #pragma unroll
            for (int p = 0; p < 4; ++p) acc[j][p] = 0ull;

        for (int s = 0; s < 24; ++s) {
            cp_wait_all();
            __syncthreads();          // stage s visible; slot (s+1)&1 free
            if (s + 1 < 24) {
                const char* nsrc = wsrc + (size_t)(s + 1) * 13824;
                unsigned int nd = offs_sh + ((s + 1) & 1) * 13824;
                for (int ch = tid; ch < 864; ch += 256)
                    cp_async16(nd + ch*16, nsrc + ch*16);
                cp_commit();
            }
            if (tid < 216) {
                const unsigned long long* wsm =
                    (const unsigned long long*)(offs + (s & 1) * 3456);
                #pragma unroll
                for (int cc = 0; cc < 4; ++cc) {
                    int c2 = s*4 + cc;
                    unsigned long long q0x = wsm[(cc*216 + cg)*2];
                    unsigned long long q0y = wsm[(cc*216 + cg)*2 + 1];
                    unsigned long long q1x = wsm[(cc*216 + cg + 54)*2];
                    unsigned long long q1y = wsm[(cc*216 + cg + 54)*2 + 1];
                    unsigned long long q2x = wsm[(cc*216 + cg + 108)*2];
                    unsigned long long q2y = wsm[(cc*216 + cg + 108)*2 + 1];
                    unsigned long long q3x = wsm[(cc*216 + cg + 162)*2];
                    unsigned long long q3y = wsm[(cc*216 + cg + 162)*2 + 1];
                    const float* ub0 = u_t + (2*c2)*34 + r0;
                    const float* ub1 = ub0 + 34;
                    #pragma unroll
                    for (int hpair = 0; hpair < 2; ++hpair) {
                        unsigned long long u0[2], u1[2];
                        #pragma unroll
                        for (int p = 0; p < 2; ++p) {
                            u0[p] = *(const unsigned long long*)(ub0 + 2*(2*hpair + p));
                            u1[p] = *(const unsigned long long*)(ub1 + 2*(2*hpair + p));
                        }
                        #pragma unroll
                        for (int p = 0; p < 2; ++p) {
                            int pp = 2*hpair + p;
                            fma2(acc[0][pp], u0[p], q0x);
                            fma2(acc[0][pp], u1[p], q0y);
                            fma2(acc[1][pp], u0[p], q1x);
                            fma2(acc[1][pp], u1[p], q1y);
                            fma2(acc[2][pp], u0[p], q2x);
                            fma2(acc[2][pp], u1[p], q2y);
                            fma2(acc[3][pp], u0[p], q3x);
                            fma2(acc[3][pp], u1[p], q3y);
                        }
                    }
                }
            }
        }
        __syncthreads();              // staging slots dead before epilogue writes

        if (tid < 216) {
            #pragma unroll
            for (int j = 0; j < 4; ++j) {
                int o = cg + 54*j;
                if (o < 144) {
                    float bb = w_delta_b[o];
                    int l = (o >> 3) % 3;
                    float sg = (l == 0) ? 4.f : ((l == 1) ? 2.f : 1.f);
                    #pragma unroll
                    for (int p = 0; p < 4; ++p) {
                        float2 v = unpack2(acc[j][p]);
                        offs[(r0 + 2*p    )*144 + o] = ftanh(v.x + bb) * sg;
                        offs[(r0 + 2*p + 1)*144 + o] = ftanh(v.y + bb) * sg;
                    }
                } else {
                    int oa = o - 144;
                    float bb = w_a_b[oa];
                    #pragma unroll
                    for (int p = 0; p < 4; ++p) {
                        float2 v = unpack2(acc[j][p]);
                        wts[(r0 + 2*p    )*72 + oa] = v.x + bb;
                        wts[(r0 + 2*p + 1)*72 + oa] = v.y + bb;
                    }
                }
            }
        }
    }
    __syncthreads();

    // ---- softmax over L*M=12 per (row, head) --------------------------------
    if (tid < 192) {
        int r = tid & 31, hh = tid >> 5;
        float* wp = wts + r*72 + hh*12;
        float mx = wp[0];
        #pragma unroll
        for (int t = 1; t < 12; ++t) mx = fmaxf(mx, wp[t]);
        float s = 0.f;
        #pragma unroll
        for (int t = 0; t < 12; ++t) { float e = __expf(wp[t] - mx); wp[t] = e; s += e; }
        float inv = 1.f / s;
        #pragma unroll
        for (int t = 0; t < 12; ++t) wp[t] *= inv;
    }
    __syncthreads();

    // ---- phase C: bilinear, branchless --------------------------------------
    {
        float* ht = u_t;                  // alias; u values dead now
        int qlane = lane >> 2;            // unit within warp
        int c8i   = lane & 3;             // channel-quarter (8 ch)
        #pragma unroll
        for (int pass = 0; pass < 3; ++pass) {
            int uu = pass*64 + wid*8 + qlane;
            int r = uu & 31, hh = uu >> 5;
            float axr = ax_s[r], ayr = ay_s[r];
            const float* op = offs + r*144 + hh*24;
            const float* wp = wts + r*72 + hh*12;
            float acc[8];
            #pragma unroll
            for (int k = 0; k < 8; ++k) acc[k] = 0.f;
            #pragma unroll
            for (int l = 0; l < 3; ++l) {
                int Hl = 128 >> l, Wl = 128 >> l;
                const uint4* ft4;
                float scl;
                if (l == 0) { ft4 = (const uint4*)d_ft0 + ((size_t)(b*NH+hh)*128*128)*4 + c8i; scl = 0.125f; }
                else if (l == 1) { ft4 = (const uint4*)d_ft1 + ((size_t)(b*NH+hh)*64*64)*4 + c8i; scl = 0.0625f; }
                else { ft4 = (const uint4*)d_ft2 + ((size_t)(b*NH+hh)*32*32)*4 + c8i; scl = 0.03125f; }
                float afx = axr*scl, afy = ayr*scl;
                #pragma unroll
                for (int m = 0; m < 4; ++m) {
                    float px = afx + op[l*8 + 2*m];
                    float py = afy + op[l*8 + 2*m + 1];
                    float wgt = wp[l*4 + m];
                    float x0f = floorf(px), y0f = floorf(py);
                    float fx = px - x0f, fy = py - y0f;
                    int x0 = (int)x0f, y0 = (int)y0f;
                    float wx0 = 1.f - fx, wy0 = 1.f - fy;
                    float cw[4] = { wgt*wx0*wy0, wgt*fx*wy0, wgt*wx0*fy, wgt*fx*fy };
                    #pragma unroll
                    for (int corner = 0; corner < 4; ++corner) {
                        int xx = x0 + (corner & 1);
                        int yy = y0 + (corner >> 1);
                        bool valid = ((unsigned)xx < (unsigned)Wl) && ((unsigned)yy < (unsigned)Hl);
                        int xc = min(max(xx, 0), Wl - 1);
                        int yc = min(max(yy, 0), Hl - 1);
                        float w = valid ? cw[corner] : 0.f;
                        uint4 raw = ft4[((size_t)yc*Wl + xc)*4];   // unconditional
                        const __half2* hp = (const __half2*)&raw;
                        #pragma unroll
                        for (int k = 0; k < 4; ++k) {
                            float2 f2 = __half22float2(hp[k]);
                            acc[2*k]   += w * f2.x;
                            acc[2*k+1] += w * f2.y;
                        }
                    }
                }
            }
            int cbase = hh*32 + c8i*8;
            #pragma unroll
            for (int k = 0; k < 8; ++k)
                ht[(cbase + k)*34 + r] = acc[k];
        }
    }
    __syncthreads();

    // ---- phase D: [32x192] @ [192x192]; staged dup-quad weights -------------
    // stage = 4 c2 x 192 float4 = 12288B; 2 slots in dead offs/wts region
    {
        float* ht = u_t;
        const char* wsrc = (const char*)d_woQ;
        unsigned int offs_sh = (unsigned int)__cvta_generic_to_shared(offs);
        for (int ch = tid; ch < 768; ch += 256)
            cp_async16(offs_sh + ch*16, wsrc + ch*16);
        cp_commit();

        int rg = tid & 3;
        int cg = tid >> 2;            // 0..47
        int r0 = rg * 8;
        unsigned long long acc[4][4];
        #pragma unroll
        for (int j = 0; j < 4; ++j)
            #pragma unroll
            for (int p = 0; p < 4; ++p) acc[j][p] = 0ull;

        for (int s = 0; s < 24; ++s) {
            cp_wait_all();
            __syncthreads();
            if (s + 1 < 24) {
                const char* nsrc = wsrc + (size_t)(s + 1) * 12288;
                unsigned int nd = offs_sh + ((s + 1) & 1) * 12288;
                for (int ch = tid; ch < 768; ch += 256)
                    cp_async16(nd + ch*16, nsrc + ch*16);
                cp_commit();
            }
            if (tid < 192) {
                const unsigned long long* wsm =
                    (const unsigned long long*)(offs + (s & 1) * 3072);
                #pragma unroll
                for (int cc = 0; cc < 4; ++cc) {
                    int c2 = s*4 + cc;
                    unsigned long long q0x = wsm[(cc*192 + cg)*2];
                    unsigned long long q0y = wsm[(cc*192 + cg)*2 + 1];
                    unsigned long long q1x = wsm[(cc*192 + cg + 48)*2];
                    unsigned long long q1y = wsm[(cc*192 + cg + 48)*2 + 1];
                    unsigned long long q2x = wsm[(cc*192 + cg + 96)*2];
                    unsigned long long q2y = wsm[(cc*192 + cg + 96)*2 + 1];
                    unsigned long long q3x = wsm[(cc*192 + cg + 144)*2];
                    unsigned long long q3y = wsm[(cc*192 + cg + 144)*2 + 1];
                    const float* ub0 = ht + (2*c2)*34 + r0;
                    const float* ub1 = ub0 + 34;
                    #pragma unroll
                    for (int hpair = 0; hpair < 2; ++hpair) {
                        unsigned long long u0[2], u1[2];
                        #pragma unroll
                        for (int p = 0; p < 2; ++p) {
                            u0[p] = *(const unsigned long long*)(ub0 + 2*(2*hpair + p));
                            u1[p] = *(const unsigned long long*)(ub1 + 2*(2*hpair + p));
                        }
                        #pragma unroll
                        for (int p = 0; p < 2; ++p) {
                            int pp = 2*hpair + p;
                            fma2(acc[0][pp], u0[p], q0x);
                            fma2(acc[0][pp], u1[p], q0y);
                            fma2(acc[1][pp], u0[p], q1x);
                            fma2(acc[1][pp], u1[p], q1y);
                            fma2(acc[2][pp], u0[p], q2x);
                            fma2(acc[2][pp], u1[p], q2y);
                            fma2(acc[3][pp], u0[p], q3x);
                            fma2(acc[3][pp], u1[p], q3y);
                        }
                    }
                }
            }
        }

        if (tid < 192) {
            #pragma unroll
            for (int j = 0; j < 4; ++j) {
                int d = cg + 48*j;
                float bb = w_o_b[d] + e_def[d];
                #pragma unroll
                for (int p = 0; p < 4; ++p) {
                    float2 v = unpack2(acc[j][p]);
                    out[((size_t)bk*RR + r0 + 2*p    )*192 + d] = v.x + bb;
                    out[((size_t)bk*RR + r0 + 2*p + 1)*192 + d] = v.y + bb;
                }
            }
        }
    }
}

// ---------------- launch ------------------------------------------------------
extern "C" void kernel_launch(void* const* d_in, const int* in_sizes, int n_in,
                              void* d_out, int out_size)
{
    const float* h     = (const float*)d_in[0];
    const int*   top   = (const int*)  d_in[1];
    const float* qc    = (const float*)d_in[2];
    const float* g     = (const float*)d_in[3];
    const float* L2p   = (const float*)d_in[4];
    const float* L3p   = (const float*)d_in[5];
    const float* L4p   = (const float*)d_in[6];
    const float* w_u_w = (const float*)d_in[7];
    const float* w_u_b = (const float*)d_in[8];
    const float* ln_g  = (const float*)d_in[9];
    const float* ln_b  = (const float*)d_in[10];
    const float* w_d_w = (const float*)d_in[11];
    const float* w_d_b = (const float*)d_in[12];
    const float* w_a_w = (const float*)d_in[13];
    const float* w_a_b = (const float*)d_in[14];
    const float* w_o_w = (const float*)d_in[15];
    const float* w_o_b = (const float*)d_in[16];
    const float* e_def = (const float*)d_in[17];
    float* out = (float*)d_out;

    // launch 0: weight prep
    wprep_kernel<<<64, 256>>>(w_u_w, w_d_w, w_a_w, w_o_w);
    // launch 1: merged precompute (g then h)
    pre_merged_kernel<<<80, 192>>>(g, h, w_u_b);
    // launch 2: merged feature transpose
    transpose_merged_kernel<<<8064, dim3(32, 8)>>>(L2p, L3p, L4p);
    // launch 3: main fused kernel (profiled slot)
    const int smem_bytes = SM_TOTF * 4;
    cudaFuncSetAttribute(main_kernel, cudaFuncAttributeMaxDynamicSharedMemorySize, smem_bytes);
    main_kernel<<<BB*KK, 256, smem_bytes>>>(top, qc, ln_g, ln_b,
                                            w_d_b, w_a_b, w_o_b, e_def, out);
}

// round 14
// speedup vs baseline: 1.2389x; 1.2389x over previous
#include <cuda_runtime.h>
#include <cuda_fp16.h>
#include <math.h>

#define BB 2
#define KK 256
#define RR 32
#define DD 192
#define NH 6
#define DH 32
#define NTOK 1024   // 32*32 L4 tokens per batch

// ---------------- scratch (device globals; no allocs allowed) ----------------
__device__ __half  d_ft0[(size_t)BB*NH*128*128*32];  // level0 channels-last fp16
__device__ __half  d_ft1[(size_t)BB*NH*64*64*32];    // level1
__device__ __half  d_ft2[(size_t)BB*NH*32*32*32];    // level2
__device__ float   d_gpre[(size_t)BB*NTOK*DD];       // g @ W_u[:,192:384]
__device__ float   d_hpre[(size_t)BB*KK*DD];         // h @ W_u[:,0:192] + b_u
__device__ float   d_wuT [(size_t)416*192];          // W_u^T  [c][d]
__device__ float2  d_wdT2[(size_t)96*216];           // delta+a weights, (c2, o){c%2}
__device__ float2  d_woT2[(size_t)96*192];           // W_o, (c2, o){c%2}

// ---------------- f32x2 packed-FMA helpers (Blackwell) ------------------------
__device__ __forceinline__ unsigned long long pack2(float x, float y) {
    unsigned long long r;
    asm("mov.b64 %0, {%1, %2};" : "=l"(r) : "f"(x), "f"(y));
    return r;
}
__device__ __forceinline__ void fma2(unsigned long long& d, unsigned long long a,
                                     unsigned long long b) {
    asm("fma.rn.f32x2 %0, %1, %2, %0;" : "+l"(d) : "l"(a), "l"(b));
}
__device__ __forceinline__ float2 unpack2(unsigned long long v) {
    float2 r;
    asm("mov.b64 {%0, %1}, %2;" : "=f"(r.x), "=f"(r.y) : "l"(v));
    return r;
}
// fast tanh via MUFU EX2 (abs err ~1e-6; exact saturation at +-inf)
__device__ __forceinline__ float ftanh(float x) {
    float e = __expf(2.f * x);
    return 1.f - __fdividef(2.f, e + 1.f);
}
// 16B async copy gmem -> smem
__device__ __forceinline__ void cp_async16(unsigned int dst, const void* src) {
    asm volatile("cp.async.ca.shared.global [%0], [%1], 16;" :: "r"(dst), "l"(src));
}
__device__ __forceinline__ void cp_commit() {
    asm volatile("cp.async.commit_group;");
}
__device__ __forceinline__ void cp_wait_all() {
    asm volatile("cp.async.wait_group 0;");
}

// ---------------- merged prep: weight layouts + feature transpose ------------
// blocks 0..63: weight prep; blocks 64..8127: feature transpose
__global__ void prep_all_kernel(const float* __restrict__ wu,
                                const float* __restrict__ wd,
                                const float* __restrict__ wa,
                                const float* __restrict__ wo,
                                const float* __restrict__ L2p,
                                const float* __restrict__ L3p,
                                const float* __restrict__ L4p)
{
    if (blockIdx.x < 64) {
        int i0 = blockIdx.x * blockDim.x + threadIdx.x;
        int stride = 64 * blockDim.x;
        for (int i = i0; i < 416*192; i += stride) {
            int c = i / 192, d = i - c*192;
            d_wuT[i] = wu[(size_t)d*416 + c];
        }
        float* wd2 = (float*)d_wdT2;
        for (int i = i0; i < 96*216*2; i += stride) {
            int c2 = i / 432; int rem = i - c2*432;
            int o = rem >> 1; int ci = rem & 1;
            int c = 2*c2 + ci;
            wd2[i] = (o < 144) ? wd[(size_t)o*192 + c] : wa[(size_t)(o-144)*192 + c];
        }
        float* wo2 = (float*)d_woT2;
        for (int i = i0; i < 96*192*2; i += stride) {
            int c2 = i / 384; int rem = i - c2*384;
            int o = rem >> 1; int ci = rem & 1;
            int c = 2*c2 + ci;
            wo2[i] = wo[(size_t)o*192 + c];
        }
        return;
    }
    // ---- transpose role ----
    __shared__ float s[32][33];
    int bid = blockIdx.x - 64;
    int tx = threadIdx.x & 31, ty = threadIdx.x >> 5;   // 32 x 8
    const float* in; __half* outp; int Hl, Wl, xb, y, bh;
    if (bid < 6144) {
        Hl = Wl = 128; in = L2p; outp = d_ft0;
        int t = bid; xb = t & 3; t >>= 2; y = t & 127; bh = t >> 7;
    } else if (bid < 7680) {
        Hl = Wl = 64; in = L3p; outp = d_ft1;
        int t = bid - 6144; xb = t & 1; t >>= 1; y = t & 63; bh = t >> 6;
    } else {
        Hl = Wl = 32; in = L4p; outp = d_ft2;
        int t = bid - 7680; xb = 0; y = t & 31; bh = t >> 5;
    }
    int x0 = xb * 32;
    int b = bh / NH, hh = bh % NH;
    const float* base = in + (((size_t)b*DD + hh*DH) * Hl + y) * Wl;
    #pragma unroll
    for (int ci = ty; ci < 32; ci += 8)
        s[ci][tx] = base[(size_t)ci * Hl * Wl + x0 + tx];
    __syncthreads();
    __half* ob = outp + (((size_t)bh * Hl + y) * Wl) * 32;
    #pragma unroll
    for (int xi = ty; xi < 32; xi += 8)
        ob[(size_t)(x0 + xi) * 32 + tx] = __float2half(s[tx][xi]);
}

// ---------------- precompute: X @ WuT slice; 8 rows/block, 320 blocks --------
// blocks 0..255: g (2048 rows, colOff 192); blocks 256..319: h (+bias)
__global__ void __launch_bounds__(192)
pre_fast_kernel(const float* __restrict__ g, const float* __restrict__ h,
                const float* __restrict__ bias)
{
    __shared__ float xs[8*192];       // row-major [r][c]
    int bx = blockIdx.x;
    const float* X; float* outp; int colOff, r0;
    bool useBias;
    if (bx < 256) { X = g; outp = d_gpre; colOff = 192; r0 = bx*8; useBias = false; }
    else          { X = h; outp = d_hpre; colOff = 0;   r0 = (bx-256)*8; useBias = true; }
    int tid = threadIdx.x;            // 0..191 = output column
    for (int i = tid; i < 8*192; i += 192)
        xs[i] = X[(size_t)r0*192 + i];
    __syncthreads();
    float acc[8];
    #pragma unroll
    for (int q = 0; q < 8; ++q) acc[q] = 0.f;
    const float* wbase = d_wuT + (size_t)colOff*192 + tid;
    #pragma unroll 4
    for (int c4 = 0; c4 < 48; ++c4) {
        float w0 = wbase[(4*c4    )*192];
        float w1 = wbase[(4*c4 + 1)*192];
        float w2 = wbase[(4*c4 + 2)*192];
        float w3 = wbase[(4*c4 + 3)*192];
        #pragma unroll
        for (int q = 0; q < 8; ++q) {
            float4 xv = *(const float4*)(&xs[q*192 + 4*c4]);
            acc[q] += xv.x*w0 + xv.y*w1 + xv.z*w2 + xv.w*w3;
        }
    }
    float bb = useBias ? bias[tid] : 0.f;
    #pragma unroll
    for (int q = 0; q < 8; ++q)
        outp[(size_t)(r0 + q)*192 + tid] = acc[q] + bb;
}

// ---------------- main fused kernel (R12: cp.async staged float2 weights) ----
#define SM_UT   0          // u_t [c*34 + r], 192*34 = 6528  (reused as ht)
#define SM_OFFS 6528       // offs [32*144] = 4608 (phi aliases; staging slots here)
#define SM_PHI  6528
#define SM_WTS  11136      // wts [32*72] = 2304 (LN partials alias; staging tail)
#define SM_AX   13440
#define SM_AY   13472
#define SM_IDX  13504
#define SM_MU   13536
#define SM_RS   13568
#define SM_TOTF 13600

__global__ void __launch_bounds__(256, 4)
main_kernel(const int*   __restrict__ top_indices,
            const float* __restrict__ qc,
            const float* __restrict__ ln_g,
            const float* __restrict__ ln_b,
            const float* __restrict__ w_delta_b,
            const float* __restrict__ w_a_b,
            const float* __restrict__ w_o_b,
            const float* __restrict__ e_def,
            float* __restrict__ out)
{
    extern __shared__ float sm[];
    float* u_t  = sm + SM_UT;     // [c*34 + r]
    float* offs = sm + SM_OFFS;
    float* phi  = sm + SM_PHI;
    float* wts  = sm + SM_WTS;
    float* ax_s = sm + SM_AX;
    float* ay_s = sm + SM_AY;
    int*   idx_s = (int*)(sm + SM_IDX);
    float* mu_s = sm + SM_MU;
    float* rs_s = sm + SM_RS;

    int tid  = threadIdx.x;
    int lane = tid & 31;
    int wid  = tid >> 5;
    int bk   = blockIdx.x;         // b*256 + k
    int b    = bk >> 8;

    // ---- anchors ----
    if (tid < 32) {
        int id = top_indices[(size_t)bk * RR + tid];
        idx_s[tid] = id;
        ax_s[tid] = (float)(id & 31) * 32.f + 16.f;
        ay_s[tid] = (float)(id >> 5) * 32.f + 16.f;
    }
    __syncthreads();

    // ---- fourier PE (fast sincos) ----
    {
        int r = tid >> 3, j = tid & 7;
        float qx = qc[(size_t)bk*2 + 0];
        float qy = qc[(size_t)bk*2 + 1];
        float dxn  = (ax_s[r] - qx) * (1.f/1024.f);
        float dyn_ = (ay_s[r] - qy) * (1.f/1024.f);
        float f = (float)(1 << j);
        float xa = (dxn  * f) * 6.283185307179586f;
        float ya = (dyn_ * f) * 6.283185307179586f;
        float sx, cx, sy, cy;
        __sincosf(xa, &sx, &cx);
        __sincosf(ya, &sy, &cy);
        phi[r*32 + j]      = sx;
        phi[r*32 + 8 + j]  = cx;
        phi[r*32 + 16 + j] = sy;
        phi[r*32 + 24 + j] = cy;
    }
    __syncthreads();

    // ---- phase A: gelu(hpre + gpre[idx] + phi @ Wphi^T), two 16-wide K-chunks
    if (tid < 192) {
        {
            float w16[16];
            #pragma unroll
            for (int i = 0; i < 16; ++i)
                w16[i] = d_wuT[(size_t)(384 + i)*192 + tid];
            #pragma unroll 2
            for (int r = 0; r < 32; ++r) {
                const float4* ph = (const float4*)(phi + r*32);
                float acc = 0.f;
                #pragma unroll
                for (int c4 = 0; c4 < 4; ++c4) {
                    float4 pv = ph[c4];
                    acc += pv.x*w16[4*c4] + pv.y*w16[4*c4+1]
                         + pv.z*w16[4*c4+2] + pv.w*w16[4*c4+3];
                }
                u_t[tid*34 + r] = acc;
            }
        }
        {
            float w16[16];
            #pragma unroll
            for (int i = 0; i < 16; ++i)
                w16[i] = d_wuT[(size_t)(400 + i)*192 + tid];
            float hbase = d_hpre[(size_t)bk*192 + tid];
            for (int rb = 0; rb < 32; rb += 4) {
                float gv[4];
                #pragma unroll
                for (int q = 0; q < 4; ++q)
                    gv[q] = d_gpre[((size_t)(b*NTOK + idx_s[rb + q])) * 192 + tid];
                #pragma unroll
                for (int q = 0; q < 4; ++q) {
                    int r = rb + q;
                    float acc = u_t[tid*34 + r] + hbase + gv[q];
                    const float4* ph = (const float4*)(phi + r*32 + 16);
                    #pragma unroll
                    for (int c4 = 0; c4 < 4; ++c4) {
                        float4 pv = ph[c4];
                        acc += pv.x*w16[4*c4] + pv.y*w16[4*c4+1]
                             + pv.z*w16[4*c4+2] + pv.w*w16[4*c4+3];
                    }
                    float gel = 0.5f * acc * (1.f + erff(acc * 0.70710678118654752f));
                    u_t[tid*34 + r] = gel;
                }
            }
        }
    }
    __syncthreads();

    // ---- LN stats ----
    {
        float s1 = 0.f, s2 = 0.f;
        int c0 = wid * 24;
        for (int cc = c0; cc < c0 + 24; ++cc) {
            float v = u_t[cc*34 + lane];
            s1 += v; s2 += v*v;
        }
        wts[wid*32 + lane]       = s1;
        wts[256 + wid*32 + lane] = s2;
    }
    __syncthreads();
    if (tid < 32) {
        float s1 = 0.f, s2 = 0.f;
        #pragma unroll
        for (int w = 0; w < 8; ++w) {
            s1 += wts[w*32 + tid];
            s2 += wts[256 + w*32 + tid];
        }
        float mu  = s1 * (1.f/192.f);
        float var = s2 * (1.f/192.f) - mu*mu;
        mu_s[tid] = mu;
        rs_s[tid] = rsqrtf(var + 1e-5f);
    }
    __syncthreads();

    // ---- LN apply ----
    if (tid < 192) {
        float gg = ln_g[tid], bb = ln_b[tid];
        #pragma unroll 4
        for (int r = 0; r < 32; ++r) {
            float v = u_t[tid*34 + r];
            u_t[tid*34 + r] = (v - mu_s[r]) * rs_s[r] * gg + bb;
        }
    }
    __syncthreads();

    // ---- phase B: [32x192] @ [192x216]; cp.async staged weights -------------
    // stage = 8 c2 x 216 float2 = 13824B; 2 slots in dead offs+wts (27648B)
    {
        const char* wsrc = (const char*)d_wdT2;
        unsigned int offs_sh = (unsigned int)__cvta_generic_to_shared(offs);
        for (int ch = tid; ch < 864; ch += 256)
            cp_async16(offs_sh + ch*16, wsrc + ch*16);
        cp_commit();

        int rg = tid & 3;
        int cg = tid >> 2;            // 0..53
        int r0 = rg * 8;
        unsigned long long acc[4][4];
        #pragma unroll
        for (int j = 0; j < 4; ++j)
            #pragma unroll
            for (int p = 0; p < 4; ++p) acc[j][p] = 0ull;

        for (int s = 0; s < 12; ++s) {
            cp_wait_all();
            __syncthreads();          // stage s visible; slot (s+1)&1 free
            if (s + 1 < 12) {
                const char* nsrc = wsrc + (size_t)(s + 1) * 13824;
                unsigned int nd = offs_sh + ((s + 1) & 1) * 13824;
                for (int ch = tid; ch < 864; ch += 256)
                    cp_async16(nd + ch*16, nsrc + ch*16);
                cp_commit();
            }
            if (tid < 216) {
                const float2* wsm = (const float2*)(offs + (s & 1) * 3456);
                #pragma unroll
                for (int cc = 0; cc < 8; ++cc) {
                    int c2 = s*8 + cc;
                    float2 wv0 = wsm[cc*216 + cg];
                    float2 wv1 = wsm[cc*216 + cg + 54];
                    float2 wv2 = wsm[cc*216 + cg + 108];
                    float2 wv3 = wsm[cc*216 + cg + 162];
                    const float* ub0 = u_t + (2*c2)*34 + r0;
                    const float* ub1 = ub0 + 34;
                    #pragma unroll
                    for (int hpair = 0; hpair < 2; ++hpair) {
                        unsigned long long u0[2], u1[2];
                        #pragma unroll
                        for (int p = 0; p < 2; ++p) {
                            u0[p] = *(const unsigned long long*)(ub0 + 2*(2*hpair + p));
                            u1[p] = *(const unsigned long long*)(ub1 + 2*(2*hpair + p));
                        }
                        #pragma unroll
                        for (int p = 0; p < 2; ++p) {
                            int pp = 2*hpair + p;
                            fma2(acc[0][pp], u0[p], pack2(wv0.x, wv0.x));
                            fma2(acc[0][pp], u1[p], pack2(wv0.y, wv0.y));
                            fma2(acc[1][pp], u0[p], pack2(wv1.x, wv1.x));
                            fma2(acc[1][pp], u1[p], pack2(wv1.y, wv1.y));
                            fma2(acc[2][pp], u0[p], pack2(wv2.x, wv2.x));
                            fma2(acc[2][pp], u1[p], pack2(wv2.y, wv2.y));
                            fma2(acc[3][pp], u0[p], pack2(wv3.x, wv3.x));
                            fma2(acc[3][pp], u1[p], pack2(wv3.y, wv3.y));
                        }
                    }
                }
            }
        }
        __syncthreads();              // staging slots dead before epilogue writes

        if (tid < 216) {
            #pragma unroll
            for (int j = 0; j < 4; ++j) {
                int o = cg + 54*j;
                if (o < 144) {
                    float bb = w_delta_b[o];
                    int l = (o >> 3) % 3;
                    float sg = (l == 0) ? 4.f : ((l == 1) ? 2.f : 1.f);
                    #pragma unroll
                    for (int p = 0; p < 4; ++p) {
                        float2 v = unpack2(acc[j][p]);
                        offs[(r0 + 2*p    )*144 + o] = ftanh(v.x + bb) * sg;
                        offs[(r0 + 2*p + 1)*144 + o] = ftanh(v.y + bb) * sg;
                    }
                } else {
                    int oa = o - 144;
                    float bb = w_a_b[oa];
                    #pragma unroll
                    for (int p = 0; p < 4; ++p) {
                        float2 v = unpack2(acc[j][p]);
                        wts[(r0 + 2*p    )*72 + oa] = v.x + bb;
                        wts[(r0 + 2*p + 1)*72 + oa] = v.y + bb;
                    }
                }
            }
        }
    }
    __syncthreads();

    // ---- softmax over L*M=12 per (row, head) --------------------------------
    if (tid < 192) {
        int r = tid & 31, hh = tid >> 5;
        float* wp = wts + r*72 + hh*12;
        float mx = wp[0];
        #pragma unroll
        for (int t = 1; t < 12; ++t) mx = fmaxf(mx, wp[t]);
        float s = 0.f;
        #pragma unroll
        for (int t = 0; t < 12; ++t) { float e = __expf(wp[t] - mx); wp[t] = e; s += e; }
        float inv = 1.f / s;
        #pragma unroll
        for (int t = 0; t < 12; ++t) wp[t] *= inv;
    }
    __syncthreads();

    // ---- phase C: bilinear, branchless --------------------------------------
    {
        float* ht = u_t;                  // alias; u values dead now
        int qlane = lane >> 2;            // unit within warp
        int c8i   = lane & 3;             // channel-quarter (8 ch)
        #pragma unroll
        for (int pass = 0; pass < 3; ++pass) {
            int uu = pass*64 + wid*8 + qlane;
            int r = uu & 31, hh = uu >> 5;
            float axr = ax_s[r], ayr = ay_s[r];
            const float* op = offs + r*144 + hh*24;
            const float* wp = wts + r*72 + hh*12;
            float acc[8];
            #pragma unroll
            for (int k = 0; k < 8; ++k) acc[k] = 0.f;
            #pragma unroll
            for (int l = 0; l < 3; ++l) {
                int Hl = 128 >> l, Wl = 128 >> l;
                const uint4* ft4;
                float scl;
                if (l == 0) { ft4 = (const uint4*)d_ft0 + ((size_t)(b*NH+hh)*128*128)*4 + c8i; scl = 0.125f; }
                else if (l == 1) { ft4 = (const uint4*)d_ft1 + ((size_t)(b*NH+hh)*64*64)*4 + c8i; scl = 0.0625f; }
                else { ft4 = (const uint4*)d_ft2 + ((size_t)(b*NH+hh)*32*32)*4 + c8i; scl = 0.03125f; }
                float afx = axr*scl, afy = ayr*scl;
                #pragma unroll
                for (int m = 0; m < 4; ++m) {
                    float px = afx + op[l*8 + 2*m];
                    float py = afy + op[l*8 + 2*m + 1];
                    float wgt = wp[l*4 + m];
                    float x0f = floorf(px), y0f = floorf(py);
                    float fx = px - x0f, fy = py - y0f;
                    int x0 = (int)x0f, y0 = (int)y0f;
                    float wx0 = 1.f - fx, wy0 = 1.f - fy;
                    float cw[4] = { wgt*wx0*wy0, wgt*fx*wy0, wgt*wx0*fy, wgt*fx*fy };
                    #pragma unroll
                    for (int corner = 0; corner < 4; ++corner) {
                        int xx = x0 + (corner & 1);
                        int yy = y0 + (corner >> 1);
                        bool valid = ((unsigned)xx < (unsigned)Wl) && ((unsigned)yy < (unsigned)Hl);
                        int xc = min(max(xx, 0), Wl - 1);
                        int yc = min(max(yy, 0), Hl - 1);
                        float w = valid ? cw[corner] : 0.f;
                        uint4 raw = ft4[((size_t)yc*Wl + xc)*4];   // unconditional
                        const __half2* hp = (const __half2*)&raw;
                        #pragma unroll
                        for (int k = 0; k < 4; ++k) {
                            float2 f2 = __half22float2(hp[k]);
                            acc[2*k]   += w * f2.x;
                            acc[2*k+1] += w * f2.y;
                        }
                    }
                }
            }
            int cbase = hh*32 + c8i*8;
            #pragma unroll
            for (int k = 0; k < 8; ++k)
                ht[(cbase + k)*34 + r] = acc[k];
        }
    }
    __syncthreads();

    // ---- phase D: [32x192] @ [192x192]; cp.async staged weights -------------
    // stage = 8 c2 x 192 float2 = 12288B; 2 slots in dead offs/wts region
    {
        float* ht = u_t;
        const char* wsrc = (const char*)d_woT2;
        unsigned int offs_sh = (unsigned int)__cvta_generic_to_shared(offs);
        for (int ch = tid; ch < 768; ch += 256)
            cp_async16(offs_sh + ch*16, wsrc + ch*16);
        cp_commit();

        int rg = tid & 3;
        int cg = tid >> 2;            // 0..47
        int r0 = rg * 8;
        unsigned long long acc[4][4];
        #pragma unroll
        for (int j = 0; j < 4; ++j)
            #pragma unroll
            for (int p = 0; p < 4; ++p) acc[j][p] = 0ull;

        for (int s = 0; s < 12; ++s) {
            cp_wait_all();
            __syncthreads();
            if (s + 1 < 12) {
                const char* nsrc = wsrc + (size_t)(s + 1) * 12288;
                unsigned int nd = offs_sh + ((s + 1) & 1) * 12288;
                for (int ch = tid; ch < 768; ch += 256)
                    cp_async16(nd + ch*16, nsrc + ch*16);
                cp_commit();
            }
            if (tid < 192) {
                const float2* wsm = (const float2*)(offs + (s & 1) * 3072);
                #pragma unroll
                for (int cc = 0; cc < 8; ++cc) {
                    int c2 = s*8 + cc;
                    float2 wv0 = wsm[cc*192 + cg];
                    float2 wv1 = wsm[cc*192 + cg + 48];
                    float2 wv2 = wsm[cc*192 + cg + 96];
                    float2 wv3 = wsm[cc*192 + cg + 144];
                    const float* ub0 = ht + (2*c2)*34 + r0;
                    const float* ub1 = ub0 + 34;
                    #pragma unroll
                    for (int hpair = 0; hpair < 2; ++hpair) {
                        unsigned long long u0[2], u1[2];
                        #pragma unroll
                        for (int p = 0; p < 2; ++p) {
                            u0[p] = *(const unsigned long long*)(ub0 + 2*(2*hpair + p));
                            u1[p] = *(const unsigned long long*)(ub1 + 2*(2*hpair + p));
                        }
                        #pragma unroll
                        for (int p = 0; p < 2; ++p) {
                            int pp = 2*hpair + p;
                            fma2(acc[0][pp], u0[p], pack2(wv0.x, wv0.x));
                            fma2(acc[0][pp], u1[p], pack2(wv0.y, wv0.y));
                            fma2(acc[1][pp], u0[p], pack2(wv1.x, wv1.x));
                            fma2(acc[1][pp], u1[p], pack2(wv1.y, wv1.y));
                            fma2(acc[2][pp], u0[p], pack2(wv2.x, wv2.x));
                            fma2(acc[2][pp], u1[p], pack2(wv2.y, wv2.y));
                            fma2(acc[3][pp], u0[p], pack2(wv3.x, wv3.x));
                            fma2(acc[3][pp], u1[p], pack2(wv3.y, wv3.y));
                        }
                    }
                }
            }
        }

        if (tid < 192) {
            #pragma unroll
            for (int j = 0; j < 4; ++j) {
                int d = cg + 48*j;
                float bb = w_o_b[d] + e_def[d];
                #pragma unroll
                for (int p = 0; p < 4; ++p) {
                    float2 v = unpack2(acc[j][p]);
                    out[((size_t)bk*RR + r0 + 2*p    )*192 + d] = v.x + bb;
                    out[((size_t)bk*RR + r0 + 2*p + 1)*192 + d] = v.y + bb;
                }
            }
        }
    }
}

// ---------------- launch ------------------------------------------------------
extern "C" void kernel_launch(void* const* d_in, const int* in_sizes, int n_in,
                              void* d_out, int out_size)
{
    const float* h     = (const float*)d_in[0];
    const int*   top   = (const int*)  d_in[1];
    const float* qc    = (const float*)d_in[2];
    const float* g     = (const float*)d_in[3];
    const float* L2p   = (const float*)d_in[4];
    const float* L3p   = (const float*)d_in[5];
    const float* L4p   = (const float*)d_in[6];
    const float* w_u_w = (const float*)d_in[7];
    const float* w_u_b = (const float*)d_in[8];
    const float* ln_g  = (const float*)d_in[9];
    const float* ln_b  = (const float*)d_in[10];
    const float* w_d_w = (const float*)d_in[11];
    const float* w_d_b = (const float*)d_in[12];
    const float* w_a_w = (const float*)d_in[13];
    const float* w_a_b = (const float*)d_in[14];
    const float* w_o_w = (const float*)d_in[15];
    const float* w_o_b = (const float*)d_in[16];
    const float* e_def = (const float*)d_in[17];
    float* out = (float*)d_out;

    // launch 0: merged weight prep + feature transpose (independent roles)
    prep_all_kernel<<<8128, 256>>>(w_u_w, w_d_w, w_a_w, w_o_w, L2p, L3p, L4p);
    // launch 1: precompute (g then h), 8 rows/block for latency hiding
    pre_fast_kernel<<<320, 192>>>(g, h, w_u_b);
    // launch 2: main fused kernel
    const int smem_bytes = SM_TOTF * 4;
    cudaFuncSetAttribute(main_kernel, cudaFuncAttributeMaxDynamicSharedMemorySize, smem_bytes);
    main_kernel<<<BB*KK, 256, smem_bytes>>>(top, qc, ln_g, ln_b,
                                            w_d_b, w_a_b, w_o_b, e_def, out);
}

// round 15
// speedup vs baseline: 1.2901x; 1.0413x over previous
#include <cuda_runtime.h>
#include <cuda_fp16.h>
#include <math.h>

#define BB 2
#define KK 256
#define RR 32
#define DD 192
#define NH 6
#define DH 32
#define NTOK 1024   // 32*32 L4 tokens per batch

// ---------------- scratch (device globals; no allocs allowed) ----------------
__device__ __half  d_ft0[(size_t)BB*NH*128*128*32];  // level0 channels-last fp16
__device__ __half  d_ft1[(size_t)BB*NH*64*64*32];    // level1
__device__ __half  d_ft2[(size_t)BB*NH*32*32*32];    // level2
__device__ float   d_gpre[(size_t)BB*NTOK*DD];       // g @ W_u[:,192:384]
__device__ float   d_hpre[(size_t)BB*KK*DD];         // h @ W_u[:,0:192] + b_u
__device__ float   d_wuT [(size_t)416*192];          // W_u^T  [c][d]
__device__ float2  d_wdT2[(size_t)96*216];           // delta+a weights, (c2, o){c%2}
__device__ float2  d_woT2[(size_t)96*192];           // W_o, (c2, o){c%2}

// ---------------- f32x2 packed-FMA helpers (Blackwell) ------------------------
__device__ __forceinline__ unsigned long long pack2(float x, float y) {
    unsigned long long r;
    asm("mov.b64 %0, {%1, %2};" : "=l"(r) : "f"(x), "f"(y));
    return r;
}
__device__ __forceinline__ void fma2(unsigned long long& d, unsigned long long a,
                                     unsigned long long b) {
    asm("fma.rn.f32x2 %0, %1, %2, %0;" : "+l"(d) : "l"(a), "l"(b));
}
__device__ __forceinline__ float2 unpack2(unsigned long long v) {
    float2 r;
    asm("mov.b64 {%0, %1}, %2;" : "=f"(r.x), "=f"(r.y) : "l"(v));
    return r;
}
// fast tanh via MUFU EX2 (abs err ~1e-6; exact saturation at +-inf)
__device__ __forceinline__ float ftanh(float x) {
    float e = __expf(2.f * x);
    return 1.f - __fdividef(2.f, e + 1.f);
}
// 16B async copy gmem -> smem
__device__ __forceinline__ void cp_async16(unsigned int dst, const void* src) {
    asm volatile("cp.async.ca.shared.global [%0], [%1], 16;" :: "r"(dst), "l"(src));
}
__device__ __forceinline__ void cp_commit() {
    asm volatile("cp.async.commit_group;");
}
__device__ __forceinline__ void cp_wait_all() {
    asm volatile("cp.async.wait_group 0;");
}

// ---------------- vectorized per-row transpose helper -------------------------
// One block handles one (bh, y) row: in[c][y][0..Wl) -> out[y][x][c], c in [0,32)
template<int WL>
__device__ __forceinline__ void transpose_row(const float* __restrict__ base,
                                              __half* __restrict__ orow,
                                              float (*s)[129], int tid)
{
    // read: 32 channels x WL floats, float4 per thread, coalesced
    const int NV = 32 * WL / 4;
    #pragma unroll
    for (int i = tid; i < NV; i += 256) {
        int c  = i / (WL/4);
        int xv = i - c * (WL/4);
        float4 v = *(const float4*)(base + (size_t)c * WL * WL + xv*4);
        s[c][xv*4 + 0] = v.x;
        s[c][xv*4 + 1] = v.y;
        s[c][xv*4 + 2] = v.z;
        s[c][xv*4 + 3] = v.w;
    }
    __syncthreads();
    // write: uint4 = 8 fp16 channels per thread; pad-129 keeps banks distinct
    const int NW = WL * 4;
    #pragma unroll
    for (int i = tid; i < NW; i += 256) {
        int x  = i >> 2;
        int c8 = (i & 3) * 8;
        __half hv[8];
        #pragma unroll
        for (int j = 0; j < 8; ++j)
            hv[j] = __float2half(s[c8 + j][x]);
        *(uint4*)(orow + (size_t)x*32 + c8) = *(const uint4*)hv;
    }
    __syncthreads();
}

// ---------------- merged prep: weight layouts + row-vectorized transpose -----
// blocks 0..63: weight prep; 64..1599: L0 rows; 1600..2367: L1; 2368..2751: L2
__global__ void prep_all_kernel(const float* __restrict__ wu,
                                const float* __restrict__ wd,
                                const float* __restrict__ wa,
                                const float* __restrict__ wo,
                                const float* __restrict__ L2p,
                                const float* __restrict__ L3p,
                                const float* __restrict__ L4p)
{
    __shared__ float s[32][129];
    int tid = threadIdx.x;
    if (blockIdx.x < 64) {
        int i0 = blockIdx.x * blockDim.x + tid;
        int stride = 64 * blockDim.x;
        for (int i = i0; i < 416*192; i += stride) {
            int c = i / 192, d = i - c*192;
            d_wuT[i] = wu[(size_t)d*416 + c];
        }
        float* wd2 = (float*)d_wdT2;
        for (int i = i0; i < 96*216*2; i += stride) {
            int c2 = i / 432; int rem = i - c2*432;
            int o = rem >> 1; int ci = rem & 1;
            int c = 2*c2 + ci;
            wd2[i] = (o < 144) ? wd[(size_t)o*192 + c] : wa[(size_t)(o-144)*192 + c];
        }
        float* wo2 = (float*)d_woT2;
        for (int i = i0; i < 96*192*2; i += stride) {
            int c2 = i / 384; int rem = i - c2*384;
            int o = rem >> 1; int ci = rem & 1;
            int c = 2*c2 + ci;
            wo2[i] = wo[(size_t)o*192 + c];
        }
        return;
    }
    int bid = blockIdx.x - 64;
    if (bid < 1536) {                    // level0: 12 bh x 128 y
        int bh = bid >> 7, y = bid & 127;
        int b = bh / NH, hh = bh % NH;
        const float* base = L2p + (((size_t)b*DD + hh*DH) * 128 + y) * 128;
        __half* orow = d_ft0 + (((size_t)bh * 128 + y) * 128) * 32;
        transpose_row<128>(base, orow, s, tid);
    } else if (bid < 2304) {             // level1: 12 bh x 64 y
        int t = bid - 1536;
        int bh = t >> 6, y = t & 63;
        int b = bh / NH, hh = bh % NH;
        const float* base = L3p + (((size_t)b*DD + hh*DH) * 64 + y) * 64;
        __half* orow = d_ft1 + (((size_t)bh * 64 + y) * 64) * 32;
        transpose_row<64>(base, orow, s, tid);
    } else {                             // level2: 12 bh x 32 y
        int t = bid - 2304;
        int bh = t >> 5, y = t & 31;
        int b = bh / NH, hh = bh % NH;
        const float* base = L4p + (((size_t)b*DD + hh*DH) * 32 + y) * 32;
        __half* orow = d_ft2 + (((size_t)bh * 32 + y) * 32) * 32;
        transpose_row<32>(base, orow, s, tid);
    }
}

// ---------------- precompute: X @ WuT slice; 8 rows/block, 320 blocks --------
__global__ void __launch_bounds__(192)
pre_fast_kernel(const float* __restrict__ g, const float* __restrict__ h,
                const float* __restrict__ bias)
{
    __shared__ float xs[8*192];       // row-major [r][c]
    int bx = blockIdx.x;
    const float* X; float* outp; int colOff, r0;
    bool useBias;
    if (bx < 256) { X = g; outp = d_gpre; colOff = 192; r0 = bx*8; useBias = false; }
    else          { X = h; outp = d_hpre; colOff = 0;   r0 = (bx-256)*8; useBias = true; }
    int tid = threadIdx.x;            // 0..191 = output column
    for (int i = tid; i < 8*192; i += 192)
        xs[i] = X[(size_t)r0*192 + i];
    __syncthreads();
    float acc[8];
    #pragma unroll
    for (int q = 0; q < 8; ++q) acc[q] = 0.f;
    const float* wbase = d_wuT + (size_t)colOff*192 + tid;
    #pragma unroll 4
    for (int c4 = 0; c4 < 48; ++c4) {
        float w0 = wbase[(4*c4    )*192];
        float w1 = wbase[(4*c4 + 1)*192];
        float w2 = wbase[(4*c4 + 2)*192];
        float w3 = wbase[(4*c4 + 3)*192];
        #pragma unroll
        for (int q = 0; q < 8; ++q) {
            float4 xv = *(const float4*)(&xs[q*192 + 4*c4]);
            acc[q] += xv.x*w0 + xv.y*w1 + xv.z*w2 + xv.w*w3;
        }
    }
    float bb = useBias ? bias[tid] : 0.f;
    #pragma unroll
    for (int q = 0; q < 8; ++q)
        outp[(size_t)(r0 + q)*192 + tid] = acc[q] + bb;
}

// ---------------- main fused kernel (R12: cp.async staged float2 weights) ----
#define SM_UT   0          // u_t [c*34 + r], 192*34 = 6528  (reused as ht)
#define SM_OFFS 6528       // offs [32*144] = 4608 (phi aliases; staging slots here)
#define SM_PHI  6528
#define SM_WTS  11136      // wts [32*72] = 2304 (LN partials alias; staging tail)
#define SM_AX   13440
#define SM_AY   13472
#define SM_IDX  13504
#define SM_MU   13536
#define SM_RS   13568
#define SM_TOTF 13600

__global__ void __launch_bounds__(256, 4)
main_kernel(const int*   __restrict__ top_indices,
            const float* __restrict__ qc,
            const float* __restrict__ ln_g,
            const float* __restrict__ ln_b,
            const float* __restrict__ w_delta_b,
            const float* __restrict__ w_a_b,
            const float* __restrict__ w_o_b,
            const float* __restrict__ e_def,
            float* __restrict__ out)
{
    extern __shared__ float sm[];
    float* u_t  = sm + SM_UT;     // [c*34 + r]
    float* offs = sm + SM_OFFS;
    float* phi  = sm + SM_PHI;
    float* wts  = sm + SM_WTS;
    float* ax_s = sm + SM_AX;
    float* ay_s = sm + SM_AY;
    int*   idx_s = (int*)(sm + SM_IDX);
    float* mu_s = sm + SM_MU;
    float* rs_s = sm + SM_RS;

    int tid  = threadIdx.x;
    int lane = tid & 31;
    int wid  = tid >> 5;
    int bk   = blockIdx.x;         // b*256 + k
    int b    = bk >> 8;

    // ---- anchors ----
    if (tid < 32) {
        int id = top_indices[(size_t)bk * RR + tid];
        idx_s[tid] = id;
        ax_s[tid] = (float)(id & 31) * 32.f + 16.f;
        ay_s[tid] = (float)(id >> 5) * 32.f + 16.f;
    }
    __syncthreads();

    // ---- fourier PE (fast sincos) ----
    {
        int r = tid >> 3, j = tid & 7;
        float qx = qc[(size_t)bk*2 + 0];
        float qy = qc[(size_t)bk*2 + 1];
        float dxn  = (ax_s[r] - qx) * (1.f/1024.f);
        float dyn_ = (ay_s[r] - qy) * (1.f/1024.f);
        float f = (float)(1 << j);
        float xa = (dxn  * f) * 6.283185307179586f;
        float ya = (dyn_ * f) * 6.283185307179586f;
        float sx, cx, sy, cy;
        __sincosf(xa, &sx, &cx);
        __sincosf(ya, &sy, &cy);
        phi[r*32 + j]      = sx;
        phi[r*32 + 8 + j]  = cx;
        phi[r*32 + 16 + j] = sy;
        phi[r*32 + 24 + j] = cy;
    }
    __syncthreads();

    // ---- phase A: gelu(hpre + gpre[idx] + phi @ Wphi^T), two 16-wide K-chunks
    if (tid < 192) {
        {
            float w16[16];
            #pragma unroll
            for (int i = 0; i < 16; ++i)
                w16[i] = d_wuT[(size_t)(384 + i)*192 + tid];
            #pragma unroll 2
            for (int r = 0; r < 32; ++r) {
                const float4* ph = (const float4*)(phi + r*32);
                float acc = 0.f;
                #pragma unroll
                for (int c4 = 0; c4 < 4; ++c4) {
                    float4 pv = ph[c4];
                    acc += pv.x*w16[4*c4] + pv.y*w16[4*c4+1]
                         + pv.z*w16[4*c4+2] + pv.w*w16[4*c4+3];
                }
                u_t[tid*34 + r] = acc;
            }
        }
        {
            float w16[16];
            #pragma unroll
            for (int i = 0; i < 16; ++i)
                w16[i] = d_wuT[(size_t)(400 + i)*192 + tid];
            float hbase = d_hpre[(size_t)bk*192 + tid];
            for (int rb = 0; rb < 32; rb += 4) {
                float gv[4];
                #pragma unroll
                for (int q = 0; q < 4; ++q)
                    gv[q] = d_gpre[((size_t)(b*NTOK + idx_s[rb + q])) * 192 + tid];
                #pragma unroll
                for (int q = 0; q < 4; ++q) {
                    int r = rb + q;
                    float acc = u_t[tid*34 + r] + hbase + gv[q];
                    const float4* ph = (const float4*)(phi + r*32 + 16);
                    #pragma unroll
                    for (int c4 = 0; c4 < 4; ++c4) {
                        float4 pv = ph[c4];
                        acc += pv.x*w16[4*c4] + pv.y*w16[4*c4+1]
                             + pv.z*w16[4*c4+2] + pv.w*w16[4*c4+3];
                    }
                    float gel = 0.5f * acc * (1.f + erff(acc * 0.70710678118654752f));
                    u_t[tid*34 + r] = gel;
                }
            }
        }
    }
    __syncthreads();

    // ---- LN stats ----
    {
        float s1 = 0.f, s2 = 0.f;
        int c0 = wid * 24;
        for (int cc = c0; cc < c0 + 24; ++cc) {
            float v = u_t[cc*34 + lane];
            s1 += v; s2 += v*v;
        }
        wts[wid*32 + lane]       = s1;
        wts[256 + wid*32 + lane] = s2;
    }
    __syncthreads();
    if (tid < 32) {
        float s1 = 0.f, s2 = 0.f;
        #pragma unroll
        for (int w = 0; w < 8; ++w) {
            s1 += wts[w*32 + tid];
            s2 += wts[256 + w*32 + tid];
        }
        float mu  = s1 * (1.f/192.f);
        float var = s2 * (1.f/192.f) - mu*mu;
        mu_s[tid] = mu;
        rs_s[tid] = rsqrtf(var + 1e-5f);
    }
    __syncthreads();

    // ---- LN apply ----
    if (tid < 192) {
        float gg = ln_g[tid], bb = ln_b[tid];
        #pragma unroll 4
        for (int r = 0; r < 32; ++r) {
            float v = u_t[tid*34 + r];
            u_t[tid*34 + r] = (v - mu_s[r]) * rs_s[r] * gg + bb;
        }
    }
    __syncthreads();

    // ---- phase B: [32x192] @ [192x216]; cp.async staged weights -------------
    // stage = 8 c2 x 216 float2 = 13824B; 2 slots in dead offs+wts (27648B)
    {
        const char* wsrc = (const char*)d_wdT2;
        unsigned int offs_sh = (unsigned int)__cvta_generic_to_shared(offs);
        for (int ch = tid; ch < 864; ch += 256)
            cp_async16(offs_sh + ch*16, wsrc + ch*16);
        cp_commit();

        int rg = tid & 3;
        int cg = tid >> 2;            // 0..53
        int r0 = rg * 8;
        unsigned long long acc[4][4];
        #pragma unroll
        for (int j = 0; j < 4; ++j)
            #pragma unroll
            for (int p = 0; p < 4; ++p) acc[j][p] = 0ull;

        for (int s = 0; s < 12; ++s) {
            cp_wait_all();
            __syncthreads();          // stage s visible; slot (s+1)&1 free
            if (s + 1 < 12) {
                const char* nsrc = wsrc + (size_t)(s + 1) * 13824;
                unsigned int nd = offs_sh + ((s + 1) & 1) * 13824;
                for (int ch = tid; ch < 864; ch += 256)
                    cp_async16(nd + ch*16, nsrc + ch*16);
                cp_commit();
            }
            if (tid < 216) {
                const float2* wsm = (const float2*)(offs + (s & 1) * 3456);
                #pragma unroll
                for (int cc = 0; cc < 8; ++cc) {
                    int c2 = s*8 + cc;
                    float2 wv0 = wsm[cc*216 + cg];
                    float2 wv1 = wsm[cc*216 + cg + 54];
                    float2 wv2 = wsm[cc*216 + cg + 108];
                    float2 wv3 = wsm[cc*216 + cg + 162];
                    const float* ub0 = u_t + (2*c2)*34 + r0;
                    const float* ub1 = ub0 + 34;
                    #pragma unroll
                    for (int hpair = 0; hpair < 2; ++hpair) {
                        unsigned long long u0[2], u1[2];
                        #pragma unroll
                        for (int p = 0; p < 2; ++p) {
                            u0[p] = *(const unsigned long long*)(ub0 + 2*(2*hpair + p));
                            u1[p] = *(const unsigned long long*)(ub1 + 2*(2*hpair + p));
                        }
                        #pragma unroll
                        for (int p = 0; p < 2; ++p) {
                            int pp = 2*hpair + p;
                            fma2(acc[0][pp], u0[p], pack2(wv0.x, wv0.x));
                            fma2(acc[0][pp], u1[p], pack2(wv0.y, wv0.y));
                            fma2(acc[1][pp], u0[p], pack2(wv1.x, wv1.x));
                            fma2(acc[1][pp], u1[p], pack2(wv1.y, wv1.y));
                            fma2(acc[2][pp], u0[p], pack2(wv2.x, wv2.x));
                            fma2(acc[2][pp], u1[p], pack2(wv2.y, wv2.y));
                            fma2(acc[3][pp], u0[p], pack2(wv3.x, wv3.x));
                            fma2(acc[3][pp], u1[p], pack2(wv3.y, wv3.y));
                        }
                    }
                }
            }
        }
        __syncthreads();              // staging slots dead before epilogue writes

        if (tid < 216) {
            #pragma unroll
            for (int j = 0; j < 4; ++j) {
                int o = cg + 54*j;
                if (o < 144) {
                    float bb = w_delta_b[o];
                    int l = (o >> 3) % 3;
                    float sg = (l == 0) ? 4.f : ((l == 1) ? 2.f : 1.f);
                    #pragma unroll
                    for (int p = 0; p < 4; ++p) {
                        float2 v = unpack2(acc[j][p]);
                        offs[(r0 + 2*p    )*144 + o] = ftanh(v.x + bb) * sg;
                        offs[(r0 + 2*p + 1)*144 + o] = ftanh(v.y + bb) * sg;
                    }
                } else {
                    int oa = o - 144;
                    float bb = w_a_b[oa];
                    #pragma unroll
                    for (int p = 0; p < 4; ++p) {
                        float2 v = unpack2(acc[j][p]);
                        wts[(r0 + 2*p    )*72 + oa] = v.x + bb;
                        wts[(r0 + 2*p + 1)*72 + oa] = v.y + bb;
                    }
                }
            }
        }
    }
    __syncthreads();

    // ---- softmax over L*M=12 per (row, head) --------------------------------
    if (tid < 192) {
        int r = tid & 31, hh = tid >> 5;
        float* wp = wts + r*72 + hh*12;
        float mx = wp[0];
        #pragma unroll
        for (int t = 1; t < 12; ++t) mx = fmaxf(mx, wp[t]);
        float s = 0.f;
        #pragma unroll
        for (int t = 0; t < 12; ++t) { float e = __expf(wp[t] - mx); wp[t] = e; s += e; }
        float inv = 1.f / s;
        #pragma unroll
        for (int t = 0; t < 12; ++t) wp[t] *= inv;
    }
    __syncthreads();

    // ---- phase C: bilinear, branchless --------------------------------------
    {
        float* ht = u_t;                  // alias; u values dead now
        int qlane = lane >> 2;            // unit within warp
        int c8i   = lane & 3;             // channel-quarter (8 ch)
        #pragma unroll
        for (int pass = 0; pass < 3; ++pass) {
            int uu = pass*64 + wid*8 + qlane;
            int r = uu & 31, hh = uu >> 5;
            float axr = ax_s[r], ayr = ay_s[r];
            const float* op = offs + r*144 + hh*24;
            const float* wp = wts + r*72 + hh*12;
            float acc[8];
            #pragma unroll
            for (int k = 0; k < 8; ++k) acc[k] = 0.f;
            #pragma unroll
            for (int l = 0; l < 3; ++l) {
                int Hl = 128 >> l, Wl = 128 >> l;
                const uint4* ft4;
                float scl;
                if (l == 0) { ft4 = (const uint4*)d_ft0 + ((size_t)(b*NH+hh)*128*128)*4 + c8i; scl = 0.125f; }
                else if (l == 1) { ft4 = (const uint4*)d_ft1 + ((size_t)(b*NH+hh)*64*64)*4 + c8i; scl = 0.0625f; }
                else { ft4 = (const uint4*)d_ft2 + ((size_t)(b*NH+hh)*32*32)*4 + c8i; scl = 0.03125f; }
                float afx = axr*scl, afy = ayr*scl;
                #pragma unroll
                for (int m = 0; m < 4; ++m) {
                    float px = afx + op[l*8 + 2*m];
                    float py = afy + op[l*8 + 2*m + 1];
                    float wgt = wp[l*4 + m];
                    float x0f = floorf(px), y0f = floorf(py);
                    float fx = px - x0f, fy = py - y0f;
                    int x0 = (int)x0f, y0 = (int)y0f;
                    float wx0 = 1.f - fx, wy0 = 1.f - fy;
                    float cw[4] = { wgt*wx0*wy0, wgt*fx*wy0, wgt*wx0*fy, wgt*fx*fy };
                    #pragma unroll
                    for (int corner = 0; corner < 4; ++corner) {
                        int xx = x0 + (corner & 1);
                        int yy = y0 + (corner >> 1);
                        bool valid = ((unsigned)xx < (unsigned)Wl) && ((unsigned)yy < (unsigned)Hl);
                        int xc = min(max(xx, 0), Wl - 1);
                        int yc = min(max(yy, 0), Hl - 1);
                        float w = valid ? cw[corner] : 0.f;
                        uint4 raw = ft4[((size_t)yc*Wl + xc)*4];   // unconditional
                        const __half2* hp = (const __half2*)&raw;
                        #pragma unroll
                        for (int k = 0; k < 4; ++k) {
                            float2 f2 = __half22float2(hp[k]);
                            acc[2*k]   += w * f2.x;
                            acc[2*k+1] += w * f2.y;
                        }
                    }
                }
            }
            int cbase = hh*32 + c8i*8;
            #pragma unroll
            for (int k = 0; k < 8; ++k)
                ht[(cbase + k)*34 + r] = acc[k];
        }
    }
    __syncthreads();

    // ---- phase D: [32x192] @ [192x192]; cp.async staged weights -------------
    // stage = 8 c2 x 192 float2 = 12288B; 2 slots in dead offs/wts region
    {
        float* ht = u_t;
        const char* wsrc = (const char*)d_woT2;
        unsigned int offs_sh = (unsigned int)__cvta_generic_to_shared(offs);
        for (int ch = tid; ch < 768; ch += 256)
            cp_async16(offs_sh + ch*16, wsrc + ch*16);
        cp_commit();

        int rg = tid & 3;
        int cg = tid >> 2;            // 0..47
        int r0 = rg * 8;
        unsigned long long acc[4][4];
        #pragma unroll
        for (int j = 0; j < 4; ++j)
            #pragma unroll
            for (int p = 0; p < 4; ++p) acc[j][p] = 0ull;

        for (int s = 0; s < 12; ++s) {
            cp_wait_all();
            __syncthreads();
            if (s + 1 < 12) {
                const char* nsrc = wsrc + (size_t)(s + 1) * 12288;
                unsigned int nd = offs_sh + ((s + 1) & 1) * 12288;
                for (int ch = tid; ch < 768; ch += 256)
                    cp_async16(nd + ch*16, nsrc + ch*16);
                cp_commit();
            }
            if (tid < 192) {
                const float2* wsm = (const float2*)(offs + (s & 1) * 3072);
                #pragma unroll
                for (int cc = 0; cc < 8; ++cc) {
                    int c2 = s*8 + cc;
                    float2 wv0 = wsm[cc*192 + cg];
                    float2 wv1 = wsm[cc*192 + cg + 48];
                    float2 wv2 = wsm[cc*192 + cg + 96];
                    float2 wv3 = wsm[cc*192 + cg + 144];
                    const float* ub0 = ht + (2*c2)*34 + r0;
                    const float* ub1 = ub0 + 34;
                    #pragma unroll
                    for (int hpair = 0; hpair < 2; ++hpair) {
                        unsigned long long u0[2], u1[2];
                        #pragma unroll
                        for (int p = 0; p < 2; ++p) {
                            u0[p] = *(const unsigned long long*)(ub0 + 2*(2*hpair + p));
                            u1[p] = *(const unsigned long long*)(ub1 + 2*(2*hpair + p));
                        }
                        #pragma unroll
                        for (int p = 0; p < 2; ++p) {
                            int pp = 2*hpair + p;
                            fma2(acc[0][pp], u0[p], pack2(wv0.x, wv0.x));
                            fma2(acc[0][pp], u1[p], pack2(wv0.y, wv0.y));
                            fma2(acc[1][pp], u0[p], pack2(wv1.x, wv1.x));
                            fma2(acc[1][pp], u1[p], pack2(wv1.y, wv1.y));
                            fma2(acc[2][pp], u0[p], pack2(wv2.x, wv2.x));
                            fma2(acc[2][pp], u1[p], pack2(wv2.y, wv2.y));
                            fma2(acc[3][pp], u0[p], pack2(wv3.x, wv3.x));
                            fma2(acc[3][pp], u1[p], pack2(wv3.y, wv3.y));
                        }
                    }
                }
            }
        }

        if (tid < 192) {
            #pragma unroll
            for (int j = 0; j < 4; ++j) {
                int d = cg + 48*j;
                float bb = w_o_b[d] + e_def[d];
                #pragma unroll
                for (int p = 0; p < 4; ++p) {
                    float2 v = unpack2(acc[j][p]);
                    out[((size_t)bk*RR + r0 + 2*p    )*192 + d] = v.x + bb;
                    out[((size_t)bk*RR + r0 + 2*p + 1)*192 + d] = v.y + bb;
                }
            }
        }
    }
}

// ---------------- launch ------------------------------------------------------
extern "C" void kernel_launch(void* const* d_in, const int* in_sizes, int n_in,
                              void* d_out, int out_size)
{
    const float* h     = (const float*)d_in[0];
    const int*   top   = (const int*)  d_in[1];
    const float* qc    = (const float*)d_in[2];
    const float* g     = (const float*)d_in[3];
    const float* L2p   = (const float*)d_in[4];
    const float* L3p   = (const float*)d_in[5];
    const float* L4p   = (const float*)d_in[6];
    const float* w_u_w = (const float*)d_in[7];
    const float* w_u_b = (const float*)d_in[8];
    const float* ln_g  = (const float*)d_in[9];
    const float* ln_b  = (const float*)d_in[10];
    const float* w_d_w = (const float*)d_in[11];
    const float* w_d_b = (const float*)d_in[12];
    const float* w_a_w = (const float*)d_in[13];
    const float* w_a_b = (const float*)d_in[14];
    const float* w_o_w = (const float*)d_in[15];
    const float* w_o_b = (const float*)d_in[16];
    const float* e_def = (const float*)d_in[17];
    float* out = (float*)d_out;

    // launch 0: merged weight prep + row-vectorized feature transpose
    prep_all_kernel<<<2752, 256>>>(w_u_w, w_d_w, w_a_w, w_o_w, L2p, L3p, L4p);
    // launch 1: precompute (g then h), 8 rows/block for latency hiding
    pre_fast_kernel<<<320, 192>>>(g, h, w_u_b);
    // launch 2: main fused kernel
    const int smem_bytes = SM_TOTF * 4;
    cudaFuncSetAttribute(main_kernel, cudaFuncAttributeMaxDynamicSharedMemorySize, smem_bytes);
    main_kernel<<<BB*KK, 256, smem_bytes>>>(top, qc, ln_g, ln_b,
                                            w_d_b, w_a_b, w_o_b, e_def, out);
}